// round 3
// baseline (speedup 1.0000x reference)
#include <cuda_runtime.h>
#include <cuda_bf16.h>

// out[b,d] = ETA*||grad_b|| * sum_{e: disease(e)=d} w_e * sim[b, sign(e)]
// sim[b,s] = (cos(H_b, S_s)+1)/2
// Strategy: counting-sort edges by disease, warp-per-disease register accumulation
// over bf16 simT rows (one 128B line per edge). No dense W.

#define Bb 64
#define Ff 512
#define Ss 8192
#define Dd 1024
#define KC 64
#define EMAX 524288

__device__ __nv_bfloat16 g_simT[(size_t)Ss * Bb];  // 1 MB, simT[s][b]
__device__ float2 g_edgeSW[EMAX];                  // sorted (sign, weight) pairs
__device__ int g_hist[Dd];
__device__ int g_binStart[Dd + 1];
__device__ int g_binCursor[Dd];
__device__ float g_sinv[Ss];
__device__ float g_hinv[Bb];
__device__ float g_gs[Bb];  // ETA * ||grad_b||

// ---------------------------------------------------------------------------
// Row norms (warp per row) + zero the disease histogram.
// ---------------------------------------------------------------------------
__global__ void norms_kernel(const float* __restrict__ sign,
                             const float* __restrict__ heat,
                             const float* __restrict__ grad) {
    int gid = blockIdx.x * blockDim.x + threadIdx.x;
    if (gid < Dd) g_hist[gid] = 0;
    int warp = gid >> 5;
    int lane = threadIdx.x & 31;
    const int total = Ss + 2 * Bb;
    if (warp >= total) return;
    const float* base;
    if (warp < Ss)           base = sign + (size_t)warp * Ff;
    else if (warp < Ss + Bb) base = heat + (size_t)(warp - Ss) * Ff;
    else                     base = grad + (size_t)(warp - Ss - Bb) * Ff;
    const float4* p = reinterpret_cast<const float4*>(base);
    float s = 0.f;
#pragma unroll
    for (int i = 0; i < Ff / 128; i++) {
        float4 v = p[lane + i * 32];
        s += v.x * v.x + v.y * v.y + v.z * v.z + v.w * v.w;
    }
#pragma unroll
    for (int o = 16; o; o >>= 1) s += __shfl_xor_sync(0xffffffff, s, o);
    if (lane == 0) {
        if (warp < Ss)           g_sinv[warp]         = 1.0f / (sqrtf(s) + 1e-8f);
        else if (warp < Ss + Bb) g_hinv[warp - Ss]    = 1.0f / (sqrtf(s) + 1e-8f);
        else                     g_gs[warp - Ss - Bb] = 0.01f * sqrtf(s);
    }
}

// ---------------------------------------------------------------------------
// Histogram of edge diseases (smem-private then merge).
// ---------------------------------------------------------------------------
__global__ void hist_kernel(const int* __restrict__ ed, int E) {
    __shared__ int h[Dd];
    for (int i = threadIdx.x; i < Dd; i += blockDim.x) h[i] = 0;
    __syncthreads();
    for (int e = blockIdx.x * blockDim.x + threadIdx.x; e < E;
         e += gridDim.x * blockDim.x)
        atomicAdd(&h[ed[e]], 1);
    __syncthreads();
    for (int i = threadIdx.x; i < Dd; i += blockDim.x)
        if (h[i]) atomicAdd(&g_hist[i], h[i]);
}

// ---------------------------------------------------------------------------
// Exclusive prefix over 1024 bins (single CTA, Hillis-Steele).
// ---------------------------------------------------------------------------
__global__ void prefix_kernel() {
    __shared__ int sm[Dd];
    int t = threadIdx.x;
    int own = g_hist[t];
    sm[t] = own;
    __syncthreads();
#pragma unroll
    for (int off = 1; off < Dd; off <<= 1) {
        int v = (t >= off) ? sm[t - off] : 0;
        __syncthreads();
        sm[t] += v;
        __syncthreads();
    }
    int excl = sm[t] - own;
    g_binStart[t] = excl;
    g_binCursor[t] = excl;
    if (t == Dd - 1) g_binStart[Dd] = sm[t];
}

// ---------------------------------------------------------------------------
// Scatter edges into disease-sorted order as (sign, weight) pairs.
// ---------------------------------------------------------------------------
__global__ void scatter_kernel(const float* __restrict__ ew,
                               const int* __restrict__ ed,
                               const int* __restrict__ es, int E) {
    for (int e = blockIdx.x * blockDim.x + threadIdx.x; e < E;
         e += gridDim.x * blockDim.x) {
        int pos = atomicAdd(&g_binCursor[ed[e]], 1);
        g_edgeSW[pos] = make_float2(__int_as_float(es[e]), ew[e]);
    }
}

// ---------------------------------------------------------------------------
// GEMM: simT[s][b] = bf16( (hinv_b*sinv_s*(H_b . S_s) + 1)*0.5 )
// 64x64 tile, 256 threads, 4x4 microtile, KC=64 chunks with register prefetch.
// ---------------------------------------------------------------------------
__global__ void __launch_bounds__(256) sim_kernel(const float* __restrict__ H,
                                                  const float* __restrict__ Sf) {
    __shared__ float As[Bb][KC + 1];
    __shared__ float Bs[64][KC + 1];
    const int s0 = blockIdx.x * 64;
    const int tid = threadIdx.x;
    const int tx = tid & 15, ty = tid >> 4;
    const int lb = tid >> 2;        // 0..63 : row
    const int lkq = tid & 3;        // quarter of the 64-wide k chunk (16 floats)
    float4 pa[4], pb[4];
    const float4* Hp = reinterpret_cast<const float4*>(H + (size_t)lb * Ff);
    const float4* Sp = reinterpret_cast<const float4*>(Sf + (size_t)(s0 + lb) * Ff);

#pragma unroll
    for (int i = 0; i < 4; i++) {
        pa[i] = Hp[lkq * 4 + i];
        pb[i] = Sp[lkq * 4 + i];
    }

    float acc[4][4] = {};
    const int NCH = Ff / KC;
    for (int c = 0; c < NCH; c++) {
        __syncthreads();
#pragma unroll
        for (int i = 0; i < 4; i++) {
            int k = lkq * 16 + 4 * i;
            As[lb][k] = pa[i].x; As[lb][k + 1] = pa[i].y;
            As[lb][k + 2] = pa[i].z; As[lb][k + 3] = pa[i].w;
            Bs[lb][k] = pb[i].x; Bs[lb][k + 1] = pb[i].y;
            Bs[lb][k + 2] = pb[i].z; Bs[lb][k + 3] = pb[i].w;
        }
        __syncthreads();
        if (c + 1 < NCH) {
            int base = ((c + 1) * KC) / 4 + lkq * 4;
#pragma unroll
            for (int i = 0; i < 4; i++) {
                pa[i] = Hp[base + i];
                pb[i] = Sp[base + i];
            }
        }
#pragma unroll 16
        for (int k = 0; k < KC; k++) {
            float a[4], bv[4];
#pragma unroll
            for (int i = 0; i < 4; i++) a[i] = As[ty * 4 + i][k];
#pragma unroll
            for (int j = 0; j < 4; j++) bv[j] = Bs[tx * 4 + j][k];
#pragma unroll
            for (int i = 0; i < 4; i++)
#pragma unroll
                for (int j = 0; j < 4; j++) acc[i][j] += a[i] * bv[j];
        }
    }

    // Epilogue: normalize, map to [0,1], write transposed bf16 rows.
    float hi[4];
#pragma unroll
    for (int i = 0; i < 4; i++) hi[i] = g_hinv[ty * 4 + i];
#pragma unroll
    for (int j = 0; j < 4; j++) {
        const int s = s0 + tx * 4 + j;
        const float sv = g_sinv[s];
        float v0 = fmaf(acc[0][j] * hi[0], sv, 1.0f) * 0.5f;
        float v1 = fmaf(acc[1][j] * hi[1], sv, 1.0f) * 0.5f;
        float v2 = fmaf(acc[2][j] * hi[2], sv, 1.0f) * 0.5f;
        float v3 = fmaf(acc[3][j] * hi[3], sv, 1.0f) * 0.5f;
        __nv_bfloat162 p0 = __floats2bfloat162_rn(v0, v1);
        __nv_bfloat162 p1 = __floats2bfloat162_rn(v2, v3);
        uint2 u;
        u.x = *reinterpret_cast<unsigned*>(&p0);
        u.y = *reinterpret_cast<unsigned*>(&p1);
        *reinterpret_cast<uint2*>(g_simT + (size_t)s * Bb + ty * 4) = u;
    }
}

// ---------------------------------------------------------------------------
// Warp-per-disease accumulation: acc[b] += w_e * simT[s_e][b] over sorted bin,
// then out[b,d] = gs_b * acc[b]. Each lane holds b = 2*lane, 2*lane+1.
// ---------------------------------------------------------------------------
__global__ void __launch_bounds__(256) accum_kernel(float* __restrict__ out) {
    const int d = (blockIdx.x * blockDim.x + threadIdx.x) >> 5;
    const int lane = threadIdx.x & 31;
    const int start = g_binStart[d];
    const int end = g_binStart[d + 1];
    float a0 = 0.f, a1 = 0.f;
    const float2* ep = g_edgeSW;
    int e = start;
    for (; e + 8 <= end; e += 8) {
        float2 edv[8];
#pragma unroll
        for (int i = 0; i < 8; i++) edv[i] = ep[e + i];
        __nv_bfloat162 sv[8];
#pragma unroll
        for (int i = 0; i < 8; i++)
            sv[i] = *reinterpret_cast<const __nv_bfloat162*>(
                g_simT + (size_t)__float_as_int(edv[i].x) * Bb + 2 * lane);
#pragma unroll
        for (int i = 0; i < 8; i++) {
            float2 f = __bfloat1622float2(sv[i]);
            a0 = fmaf(f.x, edv[i].y, a0);
            a1 = fmaf(f.y, edv[i].y, a1);
        }
    }
    for (; e < end; e++) {
        float2 edv = ep[e];
        __nv_bfloat162 s2 = *reinterpret_cast<const __nv_bfloat162*>(
            g_simT + (size_t)__float_as_int(edv.x) * Bb + 2 * lane);
        float2 f = __bfloat1622float2(s2);
        a0 = fmaf(f.x, edv.y, a0);
        a1 = fmaf(f.y, edv.y, a1);
    }
    float2 g = *reinterpret_cast<const float2*>(g_gs + 2 * lane);
    out[(size_t)(2 * lane) * Dd + d] = g.x * a0;
    out[(size_t)(2 * lane + 1) * Dd + d] = g.y * a1;
}

// ---------------------------------------------------------------------------
extern "C" void kernel_launch(void* const* d_in, const int* in_sizes, int n_in,
                              void* d_out, int out_size) {
    const float* heat = (const float*)d_in[0];  // [64,512]
    const float* grad = (const float*)d_in[1];  // [64,512]
    const float* sign = (const float*)d_in[2];  // [8192,512]
    const float* ew   = (const float*)d_in[3];  // [E]
    const int*   ed   = (const int*)d_in[4];    // [E]
    const int*   es   = (const int*)d_in[5];    // [E]
    float* out = (float*)d_out;                 // [64,1024]
    const int E = in_sizes[3];

    norms_kernel<<<(Ss + 2 * Bb) / 8, 256>>>(sign, heat, grad);
    hist_kernel<<<128, 256>>>(ed, E);
    prefix_kernel<<<1, Dd>>>();
    scatter_kernel<<<512, 256>>>(ew, ed, es, E);
    sim_kernel<<<Ss / 64, 256>>>(heat, sign);
    accum_kernel<<<Dd / 8, 256>>>(out);
}

// round 4
// speedup vs baseline: 1.4116x; 1.4116x over previous
#include <cuda_runtime.h>
#include <cuda_bf16.h>
#include <cstdint>

// out[b,d] = ETA*||grad_b|| * sum_{e: disease(e)=d} w_e * sim[b, sign(e)]
// sim[b,s] = (cos(H_b,S_s)+1)/2
// Pipeline: fused norms+bf16-normalize -> deterministic block counting sort of
// edges by disease -> tensor-core (HMMA bf16) sim GEMM -> warp-per-disease
// register accumulation.

#define Bb 64
#define Ff 512
#define Ss 8192
#define Dd 1024
#define EMAX 524288
#define NB 64
#define BSTRIDE 132  // padded words per Hn row in smem (128 data + 4 pad)

__device__ __nv_bfloat16 g_Hn[Bb * Ff];              // normalized heat, bf16
__device__ __nv_bfloat16 g_Sn[(size_t)Ss * Ff];      // normalized sign, bf16 (8MB)
__device__ __nv_bfloat16 g_simT[(size_t)Ss * Bb];    // simT[s][b], bf16 (1MB)
__device__ float2 g_edgeSW[EMAX];                    // disease-sorted (sign,weight)
__device__ int g_blockHist[NB][Dd];
__device__ int g_blockOff[NB][Dd];
__device__ int g_binStart[Dd + 1];
__device__ float g_gs[Bb];                           // ETA * ||grad_b||

// ---------------------------------------------------------------------------
// Fused norms + bf16 normalize: Sn = bf16(S/(|S|+eps)), Hn = bf16(H/(|H|+eps)),
// gs = ETA*|grad|. One warp per row.
// ---------------------------------------------------------------------------
__global__ void norms_cvt_kernel(const float* __restrict__ sign,
                                 const float* __restrict__ heat,
                                 const float* __restrict__ grad) {
    int warp = (blockIdx.x * blockDim.x + threadIdx.x) >> 5;
    int lane = threadIdx.x & 31;
    const int total = Ss + 2 * Bb;
    if (warp >= total) return;
    const float* base;
    int kind, row;
    if (warp < Ss)           { row = warp;           base = sign + (size_t)row * Ff; kind = 0; }
    else if (warp < Ss + Bb) { row = warp - Ss;      base = heat + (size_t)row * Ff; kind = 1; }
    else                     { row = warp - Ss - Bb; base = grad + (size_t)row * Ff; kind = 2; }
    const float4* p = reinterpret_cast<const float4*>(base);
    float4 v[4];
    float s = 0.f;
#pragma unroll
    for (int i = 0; i < 4; i++) {
        v[i] = p[lane + i * 32];
        s += v[i].x * v[i].x + v[i].y * v[i].y + v[i].z * v[i].z + v[i].w * v[i].w;
    }
#pragma unroll
    for (int o = 16; o; o >>= 1) s += __shfl_xor_sync(0xffffffff, s, o);
    if (kind == 2) {
        if (lane == 0) g_gs[row] = 0.01f * sqrtf(s);
        return;
    }
    const float inv = 1.0f / (sqrtf(s) + 1e-8f);
    __nv_bfloat16* dst = (kind == 0) ? (g_Sn + (size_t)row * Ff) : (g_Hn + (size_t)row * Ff);
    uint2* d2 = reinterpret_cast<uint2*>(dst);
#pragma unroll
    for (int i = 0; i < 4; i++) {
        int f = lane + i * 32;
        __nv_bfloat162 p0 = __floats2bfloat162_rn(v[i].x * inv, v[i].y * inv);
        __nv_bfloat162 p1 = __floats2bfloat162_rn(v[i].z * inv, v[i].w * inv);
        uint2 u;
        u.x = *reinterpret_cast<unsigned*>(&p0);
        u.y = *reinterpret_cast<unsigned*>(&p1);
        d2[f] = u;
    }
}

// ---------------------------------------------------------------------------
// Per-block disease histogram (smem atomics only).
// ---------------------------------------------------------------------------
__global__ void hist_kernel(const int* __restrict__ ed, int E) {
    __shared__ int h[Dd];
    for (int i = threadIdx.x; i < Dd; i += blockDim.x) h[i] = 0;
    __syncthreads();
    const int chunk = (E + NB - 1) / NB;
    const int s0 = blockIdx.x * chunk;
    const int s1 = min(E, s0 + chunk);
    for (int e = s0 + threadIdx.x; e < s1; e += blockDim.x) atomicAdd(&h[ed[e]], 1);
    __syncthreads();
    for (int i = threadIdx.x; i < Dd; i += blockDim.x) g_blockHist[blockIdx.x][i] = h[i];
}

// ---------------------------------------------------------------------------
// Bin prefix + per-(block,bin) offsets. One CTA, 1024 threads (thread = bin).
// ---------------------------------------------------------------------------
__global__ void offsets_kernel() {
    __shared__ int sm[Dd];
    const int t = threadIdx.x;
    int sum = 0;
    for (int b = 0; b < NB; b++) sum += g_blockHist[b][t];
    sm[t] = sum;
    __syncthreads();
    for (int off = 1; off < Dd; off <<= 1) {
        int v = (t >= off) ? sm[t - off] : 0;
        __syncthreads();
        sm[t] += v;
        __syncthreads();
    }
    const int incl = sm[t];
    const int excl = incl - sum;
    g_binStart[t] = excl;
    if (t == Dd - 1) g_binStart[Dd] = incl;
    int run = excl;
    for (int b = 0; b < NB; b++) {
        g_blockOff[b][t] = run;
        run += g_blockHist[b][t];
    }
}

// ---------------------------------------------------------------------------
// Scatter edges into disease-sorted order using smem cursors (no gmem atomics).
// ---------------------------------------------------------------------------
__global__ void scatter_kernel(const float* __restrict__ ew,
                               const int* __restrict__ ed,
                               const int* __restrict__ es, int E) {
    __shared__ int cur[Dd];
    for (int i = threadIdx.x; i < Dd; i += blockDim.x) cur[i] = g_blockOff[blockIdx.x][i];
    __syncthreads();
    const int chunk = (E + NB - 1) / NB;
    const int s0 = blockIdx.x * chunk;
    const int s1 = min(E, s0 + chunk);
    for (int e = s0 + threadIdx.x; e < s1; e += blockDim.x) {
        int pos = atomicAdd(&cur[ed[e]], 1);
        g_edgeSW[pos] = make_float2(__int_as_float(es[e]), ew[e]);
    }
}

// ---------------------------------------------------------------------------
// sim GEMM via mma.sync m16n8k16 bf16 (HMMA, fp32 acc).
// Grid 128 CTAs x 128 threads; warp computes 16 s-rows x all 64 b.
// A = Sn rows (LDG direct, no reuse), B = Hn staged in padded smem.
// simT[s][b] = bf16((cos+1)*0.5)
// ---------------------------------------------------------------------------
__global__ void __launch_bounds__(128) sim_kernel() {
    __shared__ unsigned Bs[64 * BSTRIDE];  // 33.8 KB
    const int tid = threadIdx.x, lane = tid & 31, w = tid >> 5;
    const int sr = blockIdx.x * 64 + w * 16;
    const int g = lane >> 2, tg = lane & 3;
    float c[8][4];
#pragma unroll
    for (int j = 0; j < 8; j++)
#pragma unroll
        for (int i = 0; i < 4; i++) c[j][i] = 0.f;

    const unsigned* SnW = reinterpret_cast<const unsigned*>(g_Sn);  // row stride 256 words
    const unsigned* HnW = reinterpret_cast<const unsigned*>(g_Hn);  // row stride 256 words
    const unsigned* r0 = SnW + (size_t)(sr + g) * 256;
    const unsigned* r1 = SnW + (size_t)(sr + g + 8) * 256;

#pragma unroll
    for (int ch = 0; ch < 2; ch++) {
        const int k0w = ch * 128;  // word offset into rows
        __syncthreads();
        for (int i = tid; i < 64 * 32; i += 128) {
            int r = i >> 5, w4 = i & 31;
            uint4 v = *reinterpret_cast<const uint4*>(HnW + r * 256 + k0w + w4 * 4);
            *reinterpret_cast<uint4*>(&Bs[r * BSTRIDE + w4 * 4]) = v;
        }
        __syncthreads();
#pragma unroll 2
        for (int kk = 0; kk < 16; kk++) {
            const int kw = k0w + kk * 8 + tg;
            unsigned a0 = r0[kw], a1 = r1[kw], a2 = r0[kw + 4], a3 = r1[kw + 4];
#pragma unroll
            for (int j = 0; j < 8; j++) {
                unsigned b0 = Bs[(8 * j + g) * BSTRIDE + kk * 8 + tg];
                unsigned b1 = Bs[(8 * j + g) * BSTRIDE + kk * 8 + tg + 4];
                asm volatile(
                    "mma.sync.aligned.m16n8k16.row.col.f32.bf16.bf16.f32 "
                    "{%0,%1,%2,%3},{%4,%5,%6,%7},{%8,%9},{%0,%1,%2,%3};"
                    : "+f"(c[j][0]), "+f"(c[j][1]), "+f"(c[j][2]), "+f"(c[j][3])
                    : "r"(a0), "r"(a1), "r"(a2), "r"(a3), "r"(b0), "r"(b1));
            }
        }
    }

    unsigned* outW = reinterpret_cast<unsigned*>(g_simT);  // row stride 32 words
#pragma unroll
    for (int j = 0; j < 8; j++) {
        float v0 = (c[j][0] + 1.f) * 0.5f, v1 = (c[j][1] + 1.f) * 0.5f;
        float v2 = (c[j][2] + 1.f) * 0.5f, v3 = (c[j][3] + 1.f) * 0.5f;
        __nv_bfloat162 p0 = __floats2bfloat162_rn(v0, v1);
        __nv_bfloat162 p1 = __floats2bfloat162_rn(v2, v3);
        const int cw = (8 * j + tg * 2) >> 1;  // word col in simT row
        outW[(size_t)(sr + g) * 32 + cw]     = *reinterpret_cast<unsigned*>(&p0);
        outW[(size_t)(sr + g + 8) * 32 + cw] = *reinterpret_cast<unsigned*>(&p1);
    }
}

// ---------------------------------------------------------------------------
// Warp-per-disease accumulation over sorted bins; lane holds b=2*lane,2*lane+1.
// ---------------------------------------------------------------------------
__global__ void __launch_bounds__(256) accum_kernel(float* __restrict__ out) {
    const int d = (blockIdx.x * blockDim.x + threadIdx.x) >> 5;
    const int lane = threadIdx.x & 31;
    const int start = g_binStart[d];
    const int end = g_binStart[d + 1];
    float a0 = 0.f, a1 = 0.f;
    const float2* ep = g_edgeSW;
    int e = start;
    for (; e + 16 <= end; e += 16) {
        float2 edv[16];
#pragma unroll
        for (int i = 0; i < 16; i++) edv[i] = ep[e + i];
        __nv_bfloat162 sv[16];
#pragma unroll
        for (int i = 0; i < 16; i++)
            sv[i] = *reinterpret_cast<const __nv_bfloat162*>(
                g_simT + (size_t)__float_as_int(edv[i].x) * Bb + 2 * lane);
#pragma unroll
        for (int i = 0; i < 16; i++) {
            float2 f = __bfloat1622float2(sv[i]);
            a0 = fmaf(f.x, edv[i].y, a0);
            a1 = fmaf(f.y, edv[i].y, a1);
        }
    }
    for (; e < end; e++) {
        float2 edv = ep[e];
        __nv_bfloat162 s2 = *reinterpret_cast<const __nv_bfloat162*>(
            g_simT + (size_t)__float_as_int(edv.x) * Bb + 2 * lane);
        float2 f = __bfloat1622float2(s2);
        a0 = fmaf(f.x, edv.y, a0);
        a1 = fmaf(f.y, edv.y, a1);
    }
    float2 gv = *reinterpret_cast<const float2*>(g_gs + 2 * lane);
    out[(size_t)(2 * lane) * Dd + d] = gv.x * a0;
    out[(size_t)(2 * lane + 1) * Dd + d] = gv.y * a1;
}

// ---------------------------------------------------------------------------
extern "C" void kernel_launch(void* const* d_in, const int* in_sizes, int n_in,
                              void* d_out, int out_size) {
    const float* heat = (const float*)d_in[0];  // [64,512]
    const float* grad = (const float*)d_in[1];  // [64,512]
    const float* sign = (const float*)d_in[2];  // [8192,512]
    const float* ew   = (const float*)d_in[3];  // [E]
    const int*   ed   = (const int*)d_in[4];    // [E]
    const int*   es   = (const int*)d_in[5];    // [E]
    float* out = (float*)d_out;                 // [64,1024]
    const int E = in_sizes[3];

    norms_cvt_kernel<<<(Ss + 2 * Bb) / 8, 256>>>(sign, heat, grad);
    hist_kernel<<<NB, 256>>>(ed, E);
    offsets_kernel<<<1, Dd>>>();
    scatter_kernel<<<NB, 256>>>(ew, ed, es, E);
    sim_kernel<<<Ss / 64, 128>>>();
    accum_kernel<<<Dd / 8, 256>>>(out);
}